// round 11
// baseline (speedup 1.0000x reference)
#include <cuda_runtime.h>
#include <cstdint>

#define NQ 32768
#define RELW 36

// rel scratch: [q][36] = relH[0..15], relW[16..31], relT[32..35]
__device__ float g_rel[NQ * RELW];

// ---------------------------------------------------------------------------
// Kernel 1: rel GEMM, scalar fp32.  P[128q x 72c] = Q @ Ecat^T.
// Ecat = [H(31)|W(31)|T(7)|0(3)].  288 threads (9 warps).
// Warp tc owns cols tc*8..tc*8+7 (ev loads = warp broadcast).
// Lane tq owns queries {tq, tq+32, tq+64, tq+96} (qv LDS: 32 consecutive
// floats = 1 phase).  Plain FFMA only — tests the R3..R8 suspicion that
// fma.rn.f32x2 inline asm was being legalized into slow code.
// ---------------------------------------------------------------------------
#define QF 129   // sQf row stride in floats (odd -> staging + mainloop conflict-free)
#define EF 73    // sEf row stride in floats
#define PP 73    // sP row stride in floats
// smem: sQf [64][129] + sEf [64][73] = 33,024 + 18,688 = 51,712 B
#define RELSMEM (64 * QF * 4 + 64 * EF * 4)

__global__ __launch_bounds__(288, 2)
void rel_gemm(const float* __restrict__ query,
              const float* __restrict__ Hemb,   // [31,64]
              const float* __restrict__ Wemb,   // [31,64]
              const float* __restrict__ Temb)   // [7,64]
{
    extern __shared__ float smf[];
    float* sQf = smf;             // [64][QF]  sQf[k][q]
    float* sEf = smf + 64 * QF;   // [64][EF]  sEf[k][c]

    const int tid   = threadIdx.x;
    const int qbase = blockIdx.x * 128;

    // stage Q transposed to k-major (coalesced gmem reads; STS stride QF=129:
    // within a warp k varies -> banks (129k+q)%32 = (k+q)%32, all distinct)
    const float* qsrc = query + (size_t)qbase * 64;
    for (int i = tid; i < 128 * 64; i += 288) {
        int q = i >> 6, k = i & 63;
        sQf[k * QF + q] = qsrc[i];
    }
    // stage Ecat k-major (banks (73k+c)%32 = (9k+c)%32, gcd(9,32)=1 -> distinct)
    for (int i = tid; i < 72 * 64; i += 288) {
        int c = i >> 6, k = i & 63;
        float v = 0.f;
        if (c < 31)      v = Hemb[c * 64 + k];
        else if (c < 62) v = Wemb[(c - 31) * 64 + k];
        else if (c < 69) v = Temb[(c - 62) * 64 + k];
        sEf[k * EF + c] = v;
    }
    __syncthreads();

    const int tq = tid & 31;    // lane -> queries tq + 32*i
    const int tc = tid >> 5;    // warp -> cols tc*8 .. tc*8+7

    float acc[4][8];
    #pragma unroll
    for (int i = 0; i < 4; i++)
        #pragma unroll
        for (int j = 0; j < 8; j++) acc[i][j] = 0.f;

    #pragma unroll 2
    for (int k = 0; k < 64; k++) {
        float qv[4], ev[8];
        #pragma unroll
        for (int i = 0; i < 4; i++) qv[i] = sQf[k * QF + tq + 32 * i];
        #pragma unroll
        for (int j = 0; j < 8; j++) ev[j] = sEf[k * EF + tc * 8 + j];
        #pragma unroll
        for (int i = 0; i < 4; i++)
            #pragma unroll
            for (int j = 0; j < 8; j++) acc[i][j] = fmaf(qv[i], ev[j], acc[i][j]);
    }

    // --- epilogue stage A: acc -> smem P matrix (reuse staging smem)
    __syncthreads();
    float* sP = smf;                        // [128][PP]
    #pragma unroll
    for (int i = 0; i < 4; i++)
        #pragma unroll
        for (int j = 0; j < 8; j++)
            sP[(tq + 32 * i) * PP + tc * 8 + j] = acc[i][j];
    __syncthreads();

    // --- epilogue stage B: branchless coalesced scatter (every slot valid)
    float* relout = g_rel + (size_t)qbase * RELW;
    for (int e = tid; e < 128 * RELW; e += 288) {
        int ql = e / RELW;
        int s  = e - ql * RELW;
        int q  = qbase + ql;
        int c;
        if (s < 16)      c = ((q >> 4) & 15) + 15 - s;            // H: h+15-kh
        else if (s < 32) c = 31 + (q & 15) + 15 - (s - 16);       // W: 31 + w+15-kw
        else             c = 62 + ((q >> 8) & 3) + 3 - (s - 32);  // T: 62 + t+3-kt
        relout[e] = sP[ql * PP + c];
    }
}

// ---------------------------------------------------------------------------
// Kernel 2: pure stream — exact R2 version (proven 38.8us @ 72% DRAM).
// ---------------------------------------------------------------------------
#define QW 16
#define SRS 40

__global__ __launch_bounds__(256)
void stream_kernel(const float* __restrict__ scores,
                   float* __restrict__ out)
{
    __shared__ float sRel[QW][SRS];

    const int bid = blockIdx.x;
    const int tid = threadIdx.x;
    const int qbase = (bid >> 6) * 1024 + ((bid >> 4) & 3) * 256 + (bid & 15) * 16;

    const float* relsrc = g_rel + (size_t)qbase * RELW;
    for (int i = tid; i < QW * RELW; i += 256) {
        int w = i / RELW;
        sRel[w][i - w * RELW] = relsrc[i];
    }
    __syncthreads();

    const int kt  = tid >> 6;
    const int kh  = (tid >> 2) & 15;
    const int kw4 = (tid & 3) << 2;

    const size_t rowbase = (size_t)qbase * 1024;
    const float4* sc4 = (const float4*)(scores + rowbase);
    float4*       ot4 = (float4*)(out + rowbase);

    #pragma unroll 8
    for (int w = 0; w < QW; w++) {
        int v = (w << 8) + tid;
        float4 s = sc4[v];
        float base = sRel[w][kh] + sRel[w][32 + kt];
        float4 rw = *(const float4*)&sRel[w][16 + kw4];
        s.x += base + rw.x;
        s.y += base + rw.y;
        s.z += base + rw.z;
        s.w += base + rw.w;
        ot4[v] = s;
    }
}

extern "C" void kernel_launch(void* const* d_in, const int* in_sizes, int n_in,
                              void* d_out, int out_size) {
    const float* query  = (const float*)d_in[0];
    const float* scores = (const float*)d_in[1];
    const float* Hemb   = (const float*)d_in[2];
    const float* Wemb   = (const float*)d_in[3];
    const float* Temb   = (const float*)d_in[4];
    float* out = (float*)d_out;

    cudaFuncSetAttribute(rel_gemm, cudaFuncAttributeMaxDynamicSharedMemorySize, RELSMEM);
    rel_gemm<<<256, 288, RELSMEM>>>(query, Hemb, Wemb, Temb);
    stream_kernel<<<2048, 256>>>(scores, out);
}